// round 7
// baseline (speedup 1.0000x reference)
#include <cuda_runtime.h>
#include <cuda_fp16.h>

#define DIM 128
#define MAXN 16384
#define SLOTS 256
#define GROWS 32     // rows per GEMM block

// ---------------- device scratch ----------------
__device__ uint4 g_projh[MAXN * 16];     // proj rows, 128 x fp16
__device__ uint4 g_feath[MAXN * 16];     // feat rows, 128 x fp16
__device__ float g_pa06[MAXN];           // 0.6 * (attn . proj[v])
__device__ int   g_deg[MAXN];            // atomic cursor == degree
__device__ int   g_esrc[MAXN * SLOTS];   // bucketed src indices
__device__ unsigned g_attnh[64];         // 0.4*attn as 64 x half2

// ---------------- GEMM: proj = feat @ W^T (+ pa06 + attn prep) --------------
// 32 rows/block, 80KB smem -> 2 blocks/SM, grid ~313.
__global__ void gemm_kernel(const float* __restrict__ feat,
                            const float* __restrict__ W,
                            const float* __restrict__ attn, int n) {
    extern __shared__ float smem[];
    float* sW = smem;                 // [k*128 + j] = W[j*128 + k]  (64KB)
    float* sF = smem + DIM * DIM;     // 32 rows x 128               (16KB)
    int tid = threadIdx.x;
    int row0 = blockIdx.x * GROWS;

    for (int i = blockIdx.x * 256 + tid; i < n; i += gridDim.x * 256)
        g_deg[i] = 0;
    if (blockIdx.x == 0 && tid < 64) {
        __half2 h = __floats2half2_rn(0.4f * attn[2 * tid], 0.4f * attn[2 * tid + 1]);
        g_attnh[tid] = *(unsigned*)&h;
    }

    for (int idx = tid; idx < DIM * DIM; idx += 256) {
        int j = idx >> 7, k = idx & 127;
        sW[k * DIM + j] = W[idx];
    }
    int nrows = n - row0; if (nrows > GROWS) nrows = GROWS;
    float4* sF4 = (float4*)sF;
    const float4* feat4 = (const float4*)feat;
    uint2* feath2 = (uint2*)g_feath;
    for (int idx = tid; idx < nrows * 32; idx += 256) {
        float4 f = feat4[row0 * 32 + idx];
        sF4[idx] = f;
        __half2 h01 = __floats2half2_rn(f.x, f.y);
        __half2 h23 = __floats2half2_rn(f.z, f.w);
        uint2 u; u.x = *(unsigned*)&h01; u.y = *(unsigned*)&h23;
        feath2[row0 * 32 + idx] = u;
    }
    __syncthreads();

    int warp = tid >> 5, lane = tid & 31;
    const float4* sW4 = (const float4*)sW;
    uint2* projh2 = (uint2*)g_projh;
    float4 av = ((const float4*)attn)[lane];

    int rb = warp * 4;                // 8 warps x 4 rows = 32 rows
    if (row0 + rb < n) {
        float4 a0 = {0.f,0.f,0.f,0.f}, a1 = a0, a2 = a0, a3 = a0;
        #pragma unroll 8
        for (int k = 0; k < DIM; k++) {
            float4 w4 = sW4[k * 32 + lane];
            float f0 = sF[(rb + 0) * DIM + k];
            float f1 = sF[(rb + 1) * DIM + k];
            float f2 = sF[(rb + 2) * DIM + k];
            float f3 = sF[(rb + 3) * DIM + k];
            a0.x += f0 * w4.x; a0.y += f0 * w4.y; a0.z += f0 * w4.z; a0.w += f0 * w4.w;
            a1.x += f1 * w4.x; a1.y += f1 * w4.y; a1.z += f1 * w4.z; a1.w += f1 * w4.w;
            a2.x += f2 * w4.x; a2.y += f2 * w4.y; a2.z += f2 * w4.z; a2.w += f2 * w4.w;
            a3.x += f3 * w4.x; a3.y += f3 * w4.y; a3.z += f3 * w4.z; a3.w += f3 * w4.w;
        }
        #pragma unroll
        for (int r = 0; r < 4; r++) {
            if (row0 + rb + r < n) {
                float4 a = (r == 0) ? a0 : (r == 1) ? a1 : (r == 2) ? a2 : a3;
                __half2 h01 = __floats2half2_rn(a.x, a.y);
                __half2 h23 = __floats2half2_rn(a.z, a.w);
                uint2 u; u.x = *(unsigned*)&h01; u.y = *(unsigned*)&h23;
                projh2[(row0 + rb + r) * 32 + lane] = u;
                float p = a.x * av.x + a.y * av.y + a.z * av.z + a.w * av.w;
                #pragma unroll
                for (int o = 16; o; o >>= 1) p += __shfl_xor_sync(0xffffffffu, p, o);
                if (lane == 0) g_pa06[row0 + rb + r] = 0.6f * p;
            }
        }
    }
}

// ---------------- single-pass bucket scatter ----------------
__global__ void scatter_kernel(const int* __restrict__ src,
                               const int* __restrict__ dst, int e) {
    int i = blockIdx.x * blockDim.x + threadIdx.x;
    int base = i * 8;
    if (base + 7 < e) {
        int4 d0 = ((const int4*)dst)[i * 2];
        int4 d1 = ((const int4*)dst)[i * 2 + 1];
        int4 s0 = ((const int4*)src)[i * 2];
        int4 s1 = ((const int4*)src)[i * 2 + 1];
        int p0 = atomicAdd(&g_deg[d0.x], 1);
        int p1 = atomicAdd(&g_deg[d0.y], 1);
        int p2 = atomicAdd(&g_deg[d0.z], 1);
        int p3 = atomicAdd(&g_deg[d0.w], 1);
        int p4 = atomicAdd(&g_deg[d1.x], 1);
        int p5 = atomicAdd(&g_deg[d1.y], 1);
        int p6 = atomicAdd(&g_deg[d1.z], 1);
        int p7 = atomicAdd(&g_deg[d1.w], 1);
        if (p0 < SLOTS) g_esrc[(d0.x << 8) + p0] = s0.x;
        if (p1 < SLOTS) g_esrc[(d0.y << 8) + p1] = s0.y;
        if (p2 < SLOTS) g_esrc[(d0.z << 8) + p2] = s0.z;
        if (p3 < SLOTS) g_esrc[(d0.w << 8) + p3] = s0.w;
        if (p4 < SLOTS) g_esrc[(d1.x << 8) + p4] = s1.x;
        if (p5 < SLOTS) g_esrc[(d1.y << 8) + p5] = s1.y;
        if (p6 < SLOTS) g_esrc[(d1.z << 8) + p6] = s1.z;
        if (p7 < SLOTS) g_esrc[(d1.w << 8) + p7] = s1.w;
    } else {
        for (int k = base; k < e; k++) {
            int d = dst[k];
            int p = atomicAdd(&g_deg[d], 1);
            if (p < SLOTS) g_esrc[(d << 8) + p] = src[k];
        }
    }
}

// ---------------- fused reduce: warp/node, 8 lanes/edge, SW pipelined --------
__global__ void reduce_kernel(const float* __restrict__ feat,
                              const float* __restrict__ eps,
                              float* __restrict__ out, int n) {
    int v = (blockIdx.x * blockDim.x + threadIdx.x) >> 5;
    if (v >= n) return;
    int lane = threadIdx.x & 31;
    int q = lane & 7;
    int g = lane >> 3;

    uint4 t0 = g_projh[v * 16 + q * 2];
    uint4 t1 = g_projh[v * 16 + q * 2 + 1];
    __half2 er[8] = { *(__half2*)&t0.x, *(__half2*)&t0.y, *(__half2*)&t0.z, *(__half2*)&t0.w,
                      *(__half2*)&t1.x, *(__half2*)&t1.y, *(__half2*)&t1.z, *(__half2*)&t1.w };
    uint4 u0 = ((const uint4*)g_attnh)[q * 2];
    uint4 u1 = ((const uint4*)g_attnh)[q * 2 + 1];
    __half2 a[8]  = { *(__half2*)&u0.x, *(__half2*)&u0.y, *(__half2*)&u0.z, *(__half2*)&u0.w,
                      *(__half2*)&u1.x, *(__half2*)&u1.y, *(__half2*)&u1.z, *(__half2*)&u1.w };
    float c_v = g_pa06[v];

    int deg = g_deg[v];
    int cnt = deg < SLOTS ? deg : SLOTS;
    const int* row = &g_esrc[v << 8];

    const __half2 zero2 = __float2half2_rn(0.f);
    __half2 acc[8] = { zero2, zero2, zero2, zero2, zero2, zero2, zero2, zero2 };

    int iters = (cnt + 3) >> 2;
    int idx = g;
    bool valid = idx < cnt;
    int u = valid ? row[idx] : 0;
    uint4 e0 = g_projh[u * 16 + q * 2];
    uint4 e1 = g_projh[u * 16 + q * 2 + 1];
    uint4 f0 = g_feath[u * 16 + q * 2];
    uint4 f1 = g_feath[u * 16 + q * 2 + 1];
    float pa_u = g_pa06[u];

    for (int it = 0; it < iters; it++) {
        int nidx = idx + 4;
        bool nvalid = nidx < cnt;
        int nu = nvalid ? row[nidx] : 0;
        uint4 ne0 = g_projh[nu * 16 + q * 2];
        uint4 ne1 = g_projh[nu * 16 + q * 2 + 1];
        uint4 nf0 = g_feath[nu * 16 + q * 2];
        uint4 nf1 = g_feath[nu * 16 + q * 2 + 1];
        float npa = g_pa06[nu];

        __half2 el[8] = { *(__half2*)&e0.x, *(__half2*)&e0.y, *(__half2*)&e0.z, *(__half2*)&e0.w,
                          *(__half2*)&e1.x, *(__half2*)&e1.y, *(__half2*)&e1.z, *(__half2*)&e1.w };
        __half2 s1ab = zero2, s2 = zero2;
        #pragma unroll
        for (int c = 0; c < 8; c++) {
            __half2 x = __hadd2(el[c], er[c]);
            s1ab = __hfma2(__habs2(x), a[c], s1ab);
            s2   = __hfma2(el[c], er[c], s2);
        }
        __half2 pk = __hadd2(__lows2half2(s1ab, s2), __highs2half2(s1ab, s2));
        #pragma unroll
        for (int o = 1; o < 8; o <<= 1) {
            unsigned pku = *(unsigned*)&pk;
            unsigned ot = __shfl_xor_sync(0xffffffffu, pku, o);
            pk = __hadd2(pk, *(__half2*)&ot);
        }
        float s1 = __low2float(pk) + pa_u + c_v;
        float s2f = __high2float(pk);
        float gate = 1.f / (1.f + __expf(-s2f));
        float w = 1.f / (1.f + __expf(-s1 * gate));
        w = valid ? w : 0.f;
        __half2 w2 = __float2half2_rn(w);

        __half2 fu[8] = { *(__half2*)&f0.x, *(__half2*)&f0.y, *(__half2*)&f0.z, *(__half2*)&f0.w,
                          *(__half2*)&f1.x, *(__half2*)&f1.y, *(__half2*)&f1.z, *(__half2*)&f1.w };
        #pragma unroll
        for (int c = 0; c < 8; c++) acc[c] = __hfma2(fu[c], w2, acc[c]);

        idx = nidx; valid = nvalid; pa_u = npa;
        e0 = ne0; e1 = ne1; f0 = nf0; f1 = nf1;
    }

    #pragma unroll
    for (int c = 0; c < 8; c++) {
        unsigned x = *(unsigned*)&acc[c];
        unsigned y = __shfl_xor_sync(0xffffffffu, x, 8);
        acc[c] = __hadd2(acc[c], *(__half2*)&y);
        x = *(unsigned*)&acc[c];
        y = __shfl_xor_sync(0xffffffffu, x, 16);
        acc[c] = __hadd2(acc[c], *(__half2*)&y);
    }

    if (lane < 8) {
        float invd = (deg > 0) ? (1.f / (float)deg) : 0.f;
        float ge = 1.f + eps[0];
        const float4* fv = &((const float4*)feat)[v * 32 + lane * 4];
        float4* ov = &((float4*)out)[v * 32 + lane * 4];
        #pragma unroll
        for (int j = 0; j < 4; j++) {
            float2 lo = __half22float2(acc[2 * j]);
            float2 hi = __half22float2(acc[2 * j + 1]);
            float4 f = fv[j];
            float4 o;
            o.x = ge * f.x + lo.x * invd;
            o.y = ge * f.y + lo.y * invd;
            o.z = ge * f.z + hi.x * invd;
            o.w = ge * f.w + hi.y * invd;
            ov[j] = o;
        }
    }
}

// ---------------- launcher ----------------
extern "C" void kernel_launch(void* const* d_in, const int* in_sizes, int n_in,
                              void* d_out, int out_size) {
    const float* feat = (const float*)d_in[0];
    const float* fcw  = (const float*)d_in[1];
    const float* attn = (const float*)d_in[2];
    const float* eps  = (const float*)d_in[3];
    const int*   src  = (const int*)d_in[4];
    const int*   dst  = (const int*)d_in[5];

    int n = in_sizes[0] / DIM;
    int e = in_sizes[4];

    size_t smem = (size_t)(DIM * DIM + GROWS * DIM) * sizeof(float);   // 80KB
    cudaFuncSetAttribute(gemm_kernel, cudaFuncAttributeMaxDynamicSharedMemorySize, (int)smem);

    // launch 1: GEMM (+ deg zero + feat->fp16 + pa06 + attn prep)
    gemm_kernel<<<(n + GROWS - 1) / GROWS, 256, smem>>>(feat, fcw, attn, n);
    // launch 2: bucket scatter
    int e8 = (e + 7) / 8;
    scatter_kernel<<<(e8 + 255) / 256, 256>>>(src, dst, e);
    // launch 3: pipelined reduce
    int red_blocks = (n * 32 + 255) / 256;
    reduce_kernel<<<red_blocks, 256>>>(feat, eps, (float*)d_out, n);

    (void)n_in; (void)out_size;
}

// round 8
// speedup vs baseline: 1.2096x; 1.2096x over previous
#include <cuda_runtime.h>
#include <cuda_fp16.h>

#define DIM 128
#define MAXN 16384
#define SLOTS 256
#define GROWS 64          // rows per GEMM block
#define GTHREADS 512      // 16 warps x 4 rows

// ---------------- device scratch ----------------
__device__ uint4 g_projh[MAXN * 16];     // proj rows, 128 x fp16
__device__ uint4 g_feath[MAXN * 16];     // feat rows, 128 x fp16
__device__ float g_pa06[MAXN];           // 0.6 * (attn . proj[v])
__device__ int   g_deg[MAXN];            // atomic cursor == degree
__device__ int   g_esrc[MAXN * SLOTS];   // bucketed src indices
__device__ unsigned g_attnh[64];         // 0.4*attn as 64 x half2

// ---------------- GEMM: proj = feat @ W^T --------------------------------
// W row-major in smem with pitch 33 float4 (swizzle-free conflict avoidance:
// bank-group of sW4[j*33+kk] = (j+kk) mod 8; lane l reads rows l+32c -> groups
// (l+kk) mod 8, distinct per lane). Lane l owns output cols {l,l+32,l+64,l+96};
// every lane computes complete dot products (no cross-lane reduction).
__global__ void __launch_bounds__(GTHREADS, 2)
gemm_kernel(const float* __restrict__ feat,
            const float* __restrict__ W,
            const float* __restrict__ attn, int n) {
    extern __shared__ float smem[];
    float4* sW4 = (float4*)smem;                    // 128 rows x 33 f4 (67.6KB)
    float*  sF  = smem + 128 * 33 * 4;              // 64 rows x 128    (32KB)
    int tid = threadIdx.x;
    int row0 = blockIdx.x * GROWS;

    for (int i = blockIdx.x * GTHREADS + tid; i < n; i += gridDim.x * GTHREADS)
        g_deg[i] = 0;
    if (blockIdx.x == 0 && tid < 64) {
        __half2 h = __floats2half2_rn(0.4f * attn[2 * tid], 0.4f * attn[2 * tid + 1]);
        g_attnh[tid] = *(unsigned*)&h;
    }

    // stage W: coalesced load, conflict-free store
    const float4* W4 = (const float4*)W;
    for (int idx = tid; idx < DIM * 32; idx += GTHREADS) {
        int j = idx >> 5, kk = idx & 31;
        sW4[j * 33 + kk] = W4[idx];
    }
    // stage feat rows (+ fp16 conversion for the reduce)
    int nrows = n - row0; if (nrows > GROWS) nrows = GROWS;
    float4* sF4 = (float4*)sF;
    const float4* feat4 = (const float4*)feat;
    uint2* feath2 = (uint2*)g_feath;
    for (int idx = tid; idx < nrows * 32; idx += GTHREADS) {
        float4 f = feat4[row0 * 32 + idx];
        sF4[idx] = f;
        __half2 h01 = __floats2half2_rn(f.x, f.y);
        __half2 h23 = __floats2half2_rn(f.z, f.w);
        uint2 u; u.x = *(unsigned*)&h01; u.y = *(unsigned*)&h23;
        feath2[row0 * 32 + idx] = u;
    }
    __syncthreads();

    int warp = tid >> 5, lane = tid & 31;
    int rb = warp * 4;                    // 16 warps x 4 rows = 64 rows
    if (row0 + rb >= n) return;

    float acc[4][4];                      // [row r][col c: j = lane+32c]
    #pragma unroll
    for (int r = 0; r < 4; r++)
        #pragma unroll
        for (int c = 0; c < 4; c++) acc[r][c] = 0.f;

    const float4* w0p = &sW4[(lane +  0) * 33];
    const float4* w1p = &sW4[(lane + 32) * 33];
    const float4* w2p = &sW4[(lane + 64) * 33];
    const float4* w3p = &sW4[(lane + 96) * 33];
    const float4* f0p = &sF4[(rb + 0) * 32];
    const float4* f1p = &sF4[(rb + 1) * 32];
    const float4* f2p = &sF4[(rb + 2) * 32];
    const float4* f3p = &sF4[(rb + 3) * 32];

    #pragma unroll 4
    for (int kk = 0; kk < 32; kk++) {
        float4 w0 = w0p[kk], w1 = w1p[kk], w2 = w2p[kk], w3 = w3p[kk];
        float4 f0 = f0p[kk], f1 = f1p[kk], f2 = f2p[kk], f3 = f3p[kk];
        #pragma unroll
        for (int r = 0; r < 4; r++) {
            float4 f = (r == 0) ? f0 : (r == 1) ? f1 : (r == 2) ? f2 : f3;
            acc[r][0] += f.x * w0.x + f.y * w0.y + f.z * w0.z + f.w * w0.w;
            acc[r][1] += f.x * w1.x + f.y * w1.y + f.z * w1.z + f.w * w1.w;
            acc[r][2] += f.x * w2.x + f.y * w2.y + f.z * w2.z + f.w * w2.w;
            acc[r][3] += f.x * w3.x + f.y * w3.y + f.z * w3.z + f.w * w3.w;
        }
    }

    float a0 = attn[lane], a1 = attn[lane + 32], a2 = attn[lane + 64], a3 = attn[lane + 96];
    __half* projh = (__half*)g_projh;
    #pragma unroll
    for (int r = 0; r < 4; r++) {
        int row = row0 + rb + r;
        if (row < n) {
            projh[row * DIM + lane +  0] = __float2half(acc[r][0]);
            projh[row * DIM + lane + 32] = __float2half(acc[r][1]);
            projh[row * DIM + lane + 64] = __float2half(acc[r][2]);
            projh[row * DIM + lane + 96] = __float2half(acc[r][3]);
            float p = acc[r][0] * a0 + acc[r][1] * a1 + acc[r][2] * a2 + acc[r][3] * a3;
            #pragma unroll
            for (int o = 16; o; o >>= 1) p += __shfl_xor_sync(0xffffffffu, p, o);
            if (lane == 0) g_pa06[row] = 0.6f * p;
        }
    }
}

// ---------------- single-pass bucket scatter ----------------
__global__ void scatter_kernel(const int* __restrict__ src,
                               const int* __restrict__ dst, int e) {
    int i = blockIdx.x * blockDim.x + threadIdx.x;
    int base = i * 8;
    if (base + 7 < e) {
        int4 d0 = ((const int4*)dst)[i * 2];
        int4 d1 = ((const int4*)dst)[i * 2 + 1];
        int4 s0 = ((const int4*)src)[i * 2];
        int4 s1 = ((const int4*)src)[i * 2 + 1];
        int p0 = atomicAdd(&g_deg[d0.x], 1);
        int p1 = atomicAdd(&g_deg[d0.y], 1);
        int p2 = atomicAdd(&g_deg[d0.z], 1);
        int p3 = atomicAdd(&g_deg[d0.w], 1);
        int p4 = atomicAdd(&g_deg[d1.x], 1);
        int p5 = atomicAdd(&g_deg[d1.y], 1);
        int p6 = atomicAdd(&g_deg[d1.z], 1);
        int p7 = atomicAdd(&g_deg[d1.w], 1);
        if (p0 < SLOTS) g_esrc[(d0.x << 8) + p0] = s0.x;
        if (p1 < SLOTS) g_esrc[(d0.y << 8) + p1] = s0.y;
        if (p2 < SLOTS) g_esrc[(d0.z << 8) + p2] = s0.z;
        if (p3 < SLOTS) g_esrc[(d0.w << 8) + p3] = s0.w;
        if (p4 < SLOTS) g_esrc[(d1.x << 8) + p4] = s1.x;
        if (p5 < SLOTS) g_esrc[(d1.y << 8) + p5] = s1.y;
        if (p6 < SLOTS) g_esrc[(d1.z << 8) + p6] = s1.z;
        if (p7 < SLOTS) g_esrc[(d1.w << 8) + p7] = s1.w;
    } else {
        for (int k = base; k < e; k++) {
            int d = dst[k];
            int p = atomicAdd(&g_deg[d], 1);
            if (p < SLOTS) g_esrc[(d << 8) + p] = src[k];
        }
    }
}

// ---------------- fused reduce: warp/node, 8 lanes/edge, SW pipelined --------
__global__ void reduce_kernel(const float* __restrict__ feat,
                              const float* __restrict__ eps,
                              float* __restrict__ out, int n) {
    int v = (blockIdx.x * blockDim.x + threadIdx.x) >> 5;
    if (v >= n) return;
    int lane = threadIdx.x & 31;
    int q = lane & 7;
    int g = lane >> 3;

    uint4 t0 = g_projh[v * 16 + q * 2];
    uint4 t1 = g_projh[v * 16 + q * 2 + 1];
    __half2 er[8] = { *(__half2*)&t0.x, *(__half2*)&t0.y, *(__half2*)&t0.z, *(__half2*)&t0.w,
                      *(__half2*)&t1.x, *(__half2*)&t1.y, *(__half2*)&t1.z, *(__half2*)&t1.w };
    uint4 u0 = ((const uint4*)g_attnh)[q * 2];
    uint4 u1 = ((const uint4*)g_attnh)[q * 2 + 1];
    __half2 a[8]  = { *(__half2*)&u0.x, *(__half2*)&u0.y, *(__half2*)&u0.z, *(__half2*)&u0.w,
                      *(__half2*)&u1.x, *(__half2*)&u1.y, *(__half2*)&u1.z, *(__half2*)&u1.w };
    float c_v = g_pa06[v];

    int deg = g_deg[v];
    int cnt = deg < SLOTS ? deg : SLOTS;
    const int* row = &g_esrc[v << 8];

    const __half2 zero2 = __float2half2_rn(0.f);
    __half2 acc[8] = { zero2, zero2, zero2, zero2, zero2, zero2, zero2, zero2 };

    int iters = (cnt + 3) >> 2;
    int idx = g;
    bool valid = idx < cnt;
    int u = valid ? row[idx] : 0;
    uint4 e0 = g_projh[u * 16 + q * 2];
    uint4 e1 = g_projh[u * 16 + q * 2 + 1];
    uint4 f0 = g_feath[u * 16 + q * 2];
    uint4 f1 = g_feath[u * 16 + q * 2 + 1];
    float pa_u = g_pa06[u];

    for (int it = 0; it < iters; it++) {
        int nidx = idx + 4;
        bool nvalid = nidx < cnt;
        int nu = nvalid ? row[nidx] : 0;
        uint4 ne0 = g_projh[nu * 16 + q * 2];
        uint4 ne1 = g_projh[nu * 16 + q * 2 + 1];
        uint4 nf0 = g_feath[nu * 16 + q * 2];
        uint4 nf1 = g_feath[nu * 16 + q * 2 + 1];
        float npa = g_pa06[nu];

        __half2 el[8] = { *(__half2*)&e0.x, *(__half2*)&e0.y, *(__half2*)&e0.z, *(__half2*)&e0.w,
                          *(__half2*)&e1.x, *(__half2*)&e1.y, *(__half2*)&e1.z, *(__half2*)&e1.w };
        __half2 s1ab = zero2, s2 = zero2;
        #pragma unroll
        for (int c = 0; c < 8; c++) {
            __half2 x = __hadd2(el[c], er[c]);
            s1ab = __hfma2(__habs2(x), a[c], s1ab);
            s2   = __hfma2(el[c], er[c], s2);
        }
        __half2 pk = __hadd2(__lows2half2(s1ab, s2), __highs2half2(s1ab, s2));
        #pragma unroll
        for (int o = 1; o < 8; o <<= 1) {
            unsigned pku = *(unsigned*)&pk;
            unsigned ot = __shfl_xor_sync(0xffffffffu, pku, o);
            pk = __hadd2(pk, *(__half2*)&ot);
        }
        float s1 = __low2float(pk) + pa_u + c_v;
        float s2f = __high2float(pk);
        float gate = 1.f / (1.f + __expf(-s2f));
        float w = 1.f / (1.f + __expf(-s1 * gate));
        w = valid ? w : 0.f;
        __half2 w2 = __float2half2_rn(w);

        __half2 fu[8] = { *(__half2*)&f0.x, *(__half2*)&f0.y, *(__half2*)&f0.z, *(__half2*)&f0.w,
                          *(__half2*)&f1.x, *(__half2*)&f1.y, *(__half2*)&f1.z, *(__half2*)&f1.w };
        #pragma unroll
        for (int c = 0; c < 8; c++) acc[c] = __hfma2(fu[c], w2, acc[c]);

        idx = nidx; valid = nvalid; pa_u = npa;
        e0 = ne0; e1 = ne1; f0 = nf0; f1 = nf1;
    }

    #pragma unroll
    for (int c = 0; c < 8; c++) {
        unsigned x = *(unsigned*)&acc[c];
        unsigned y = __shfl_xor_sync(0xffffffffu, x, 8);
        acc[c] = __hadd2(acc[c], *(__half2*)&y);
        x = *(unsigned*)&acc[c];
        y = __shfl_xor_sync(0xffffffffu, x, 16);
        acc[c] = __hadd2(acc[c], *(__half2*)&y);
    }

    if (lane < 8) {
        float invd = (deg > 0) ? (1.f / (float)deg) : 0.f;
        float ge = 1.f + eps[0];
        const float4* fv = &((const float4*)feat)[v * 32 + lane * 4];
        float4* ov = &((float4*)out)[v * 32 + lane * 4];
        #pragma unroll
        for (int j = 0; j < 4; j++) {
            float2 lo = __half22float2(acc[2 * j]);
            float2 hi = __half22float2(acc[2 * j + 1]);
            float4 f = fv[j];
            float4 o;
            o.x = ge * f.x + lo.x * invd;
            o.y = ge * f.y + lo.y * invd;
            o.z = ge * f.z + hi.x * invd;
            o.w = ge * f.w + hi.y * invd;
            ov[j] = o;
        }
    }
}

// ---------------- launcher ----------------
extern "C" void kernel_launch(void* const* d_in, const int* in_sizes, int n_in,
                              void* d_out, int out_size) {
    const float* feat = (const float*)d_in[0];
    const float* fcw  = (const float*)d_in[1];
    const float* attn = (const float*)d_in[2];
    const float* eps  = (const float*)d_in[3];
    const int*   src  = (const int*)d_in[4];
    const int*   dst  = (const int*)d_in[5];

    int n = in_sizes[0] / DIM;
    int e = in_sizes[4];

    size_t smem = (size_t)(128 * 33 * 4 + GROWS * DIM) * sizeof(float);   // ~100KB
    cudaFuncSetAttribute(gemm_kernel, cudaFuncAttributeMaxDynamicSharedMemorySize, (int)smem);

    // launch 1: GEMM (+ deg zero + feat->fp16 + pa06 + attn prep)
    gemm_kernel<<<(n + GROWS - 1) / GROWS, GTHREADS, smem>>>(feat, fcw, attn, n);
    // launch 2: bucket scatter
    int e8 = (e + 7) / 8;
    scatter_kernel<<<(e8 + 255) / 256, 256>>>(src, dst, e);
    // launch 3: pipelined reduce
    int red_blocks = (n * 32 + 255) / 256;
    reduce_kernel<<<red_blocks, 256>>>(feat, eps, (float*)d_out, n);

    (void)n_in; (void)out_size;
}

// round 9
// speedup vs baseline: 1.3404x; 1.1082x over previous
#include <cuda_runtime.h>
#include <cuda_fp16.h>
#include <mma.h>

using namespace nvcuda;

#define DIM 128
#define MAXN 16384
#define SLOTS 256
#define GROWS 128         // rows per GEMM block (8 warps x 16)
#define GTHREADS 256
#define SPITCH 136        // half pitch for smem tiles

// ---------------- device scratch ----------------
__device__ float g_proj[MAXN * DIM];     // fp32 proj scratch (wmma store target)
__device__ uint4 g_projh[MAXN * 16];     // proj rows, 128 x fp16
__device__ uint4 g_feath[MAXN * 16];     // feat rows, 128 x fp16
__device__ float g_pa06[MAXN];           // 0.6 * (attn . proj[v])
__device__ int   g_deg[MAXN];            // atomic cursor == degree
__device__ int   g_esrc[MAXN * SLOTS];   // bucketed src indices
__device__ unsigned g_attnh[64];         // 0.4*attn as 64 x half2

// ---------------- GEMM via tensor cores: proj = feat @ W^T ------------------
__global__ void __launch_bounds__(GTHREADS, 2)
gemm_kernel(const float* __restrict__ feat,
            const float* __restrict__ W,
            const float* __restrict__ attn, int n) {
    extern __shared__ __half smem_h[];
    __half* sW = smem_h;                  // 128 x SPITCH half  (W row-major)
    __half* sA = smem_h + DIM * SPITCH;   // 128 x SPITCH half  (feat rows)
    int tid = threadIdx.x;
    int row0 = blockIdx.x * GROWS;
    int warp = tid >> 5, lane = tid & 31;

    for (int i = blockIdx.x * GTHREADS + tid; i < n; i += gridDim.x * GTHREADS)
        g_deg[i] = 0;
    if (blockIdx.x == 0 && tid < 64) {
        __half2 h = __floats2half2_rn(0.4f * attn[2 * tid], 0.4f * attn[2 * tid + 1]);
        g_attnh[tid] = *(unsigned*)&h;
    }

    // stage W -> fp16 smem (row-major, pitch SPITCH)
    const float2* W2 = (const float2*)W;
    for (int idx = tid; idx < DIM * 64; idx += GTHREADS) {
        int j = idx >> 6, k2 = idx & 63;
        float2 w = W2[idx];
        ((__half2*)(sW + j * SPITCH))[k2] = __floats2half2_rn(w.x, w.y);
    }
    // stage feat rows -> fp16 smem (+ write g_feath)
    int nrows = n - row0; if (nrows > GROWS) nrows = GROWS;
    const float2* feat2 = (const float2*)feat;
    unsigned* feath = (unsigned*)g_feath;
    for (int idx = tid; idx < GROWS * 64; idx += GTHREADS) {
        int r = idx >> 6, k2 = idx & 63;
        __half2 h = __float2half2_rn(0.f);
        if (r < nrows) {
            float2 f = feat2[(row0 + r) * 64 + k2];
            h = __floats2half2_rn(f.x, f.y);
            feath[(row0 + r) * 64 + k2] = *(unsigned*)&h;
        }
        ((__half2*)(sA + r * SPITCH))[k2] = h;
    }
    __syncthreads();

    // each warp computes 16 rows x 128 cols
    wmma::fragment<wmma::accumulator, 16, 16, 16, float> acc[8];
    #pragma unroll
    for (int j = 0; j < 8; j++) wmma::fill_fragment(acc[j], 0.f);

    #pragma unroll
    for (int kk = 0; kk < 8; kk++) {
        wmma::fragment<wmma::matrix_a, 16, 16, 16, __half, wmma::row_major> af;
        wmma::load_matrix_sync(af, sA + (warp * 16) * SPITCH + kk * 16, SPITCH);
        #pragma unroll
        for (int j = 0; j < 8; j++) {
            wmma::fragment<wmma::matrix_b, 16, 16, 16, __half, wmma::col_major> bf;
            wmma::load_matrix_sync(bf, sW + (j * 16) * SPITCH + kk * 16, SPITCH);
            wmma::mma_sync(acc[j], af, bf, acc[j]);
        }
    }
    #pragma unroll
    for (int j = 0; j < 8; j++)
        wmma::store_matrix_sync(g_proj + (row0 + warp * 16) * DIM + j * 16,
                                acc[j], DIM, wmma::mem_row_major);
    __syncthreads();   // global writes visible block-wide

    // epilogue: fp16 pack + pa06
    float4 av = ((const float4*)attn)[lane];
    uint2* projh2 = (uint2*)g_projh;
    for (int i = 0; i < 16; i++) {
        int row = row0 + warp * 16 + i;
        if (row < n) {
            float4 a = ((const float4*)g_proj)[row * 32 + lane];
            __half2 h01 = __floats2half2_rn(a.x, a.y);
            __half2 h23 = __floats2half2_rn(a.z, a.w);
            uint2 u; u.x = *(unsigned*)&h01; u.y = *(unsigned*)&h23;
            projh2[row * 32 + lane] = u;
            float p = a.x * av.x + a.y * av.y + a.z * av.z + a.w * av.w;
            #pragma unroll
            for (int o = 16; o; o >>= 1) p += __shfl_xor_sync(0xffffffffu, p, o);
            if (lane == 0) g_pa06[row] = 0.6f * p;
        }
    }
}

// ---------------- single-pass bucket scatter (16 chains/thread) -------------
__global__ void scatter_kernel(const int* __restrict__ src,
                               const int* __restrict__ dst, int e) {
    int i = blockIdx.x * blockDim.x + threadIdx.x;
    int base = i * 16;
    if (base + 15 < e) {
        int4 d[4], s[4];
        #pragma unroll
        for (int b = 0; b < 4; b++) {
            d[b] = ((const int4*)dst)[i * 4 + b];
            s[b] = ((const int4*)src)[i * 4 + b];
        }
        int p[16];
        #pragma unroll
        for (int b = 0; b < 4; b++) {
            p[b*4+0] = atomicAdd(&g_deg[d[b].x], 1);
            p[b*4+1] = atomicAdd(&g_deg[d[b].y], 1);
            p[b*4+2] = atomicAdd(&g_deg[d[b].z], 1);
            p[b*4+3] = atomicAdd(&g_deg[d[b].w], 1);
        }
        #pragma unroll
        for (int b = 0; b < 4; b++) {
            if (p[b*4+0] < SLOTS) g_esrc[(d[b].x << 8) + p[b*4+0]] = s[b].x;
            if (p[b*4+1] < SLOTS) g_esrc[(d[b].y << 8) + p[b*4+1]] = s[b].y;
            if (p[b*4+2] < SLOTS) g_esrc[(d[b].z << 8) + p[b*4+2]] = s[b].z;
            if (p[b*4+3] < SLOTS) g_esrc[(d[b].w << 8) + p[b*4+3]] = s[b].w;
        }
    } else {
        for (int k = base; k < e; k++) {
            int dd = dst[k];
            int pp = atomicAdd(&g_deg[dd], 1);
            if (pp < SLOTS) g_esrc[(dd << 8) + pp] = src[k];
        }
    }
}

// ---------------- fused reduce: warp/node, 8 lanes/edge, SW pipelined --------
__global__ void reduce_kernel(const float* __restrict__ feat,
                              const float* __restrict__ eps,
                              float* __restrict__ out, int n) {
    int v = (blockIdx.x * blockDim.x + threadIdx.x) >> 5;
    if (v >= n) return;
    int lane = threadIdx.x & 31;
    int q = lane & 7;
    int g = lane >> 3;

    uint4 t0 = g_projh[v * 16 + q * 2];
    uint4 t1 = g_projh[v * 16 + q * 2 + 1];
    __half2 er[8] = { *(__half2*)&t0.x, *(__half2*)&t0.y, *(__half2*)&t0.z, *(__half2*)&t0.w,
                      *(__half2*)&t1.x, *(__half2*)&t1.y, *(__half2*)&t1.z, *(__half2*)&t1.w };
    uint4 u0 = ((const uint4*)g_attnh)[q * 2];
    uint4 u1 = ((const uint4*)g_attnh)[q * 2 + 1];
    __half2 a[8]  = { *(__half2*)&u0.x, *(__half2*)&u0.y, *(__half2*)&u0.z, *(__half2*)&u0.w,
                      *(__half2*)&u1.x, *(__half2*)&u1.y, *(__half2*)&u1.z, *(__half2*)&u1.w };
    float c_v = g_pa06[v];

    int deg = g_deg[v];
    int cnt = deg < SLOTS ? deg : SLOTS;
    const int* row = &g_esrc[v << 8];

    const __half2 zero2 = __float2half2_rn(0.f);
    __half2 acc[8] = { zero2, zero2, zero2, zero2, zero2, zero2, zero2, zero2 };

    int iters = (cnt + 3) >> 2;
    int idx = g;
    bool valid = idx < cnt;
    int u = valid ? row[idx] : 0;
    uint4 e0 = g_projh[u * 16 + q * 2];
    uint4 e1 = g_projh[u * 16 + q * 2 + 1];
    uint4 f0 = g_feath[u * 16 + q * 2];
    uint4 f1 = g_feath[u * 16 + q * 2 + 1];
    float pa_u = g_pa06[u];

    for (int it = 0; it < iters; it++) {
        int nidx = idx + 4;
        bool nvalid = nidx < cnt;
        int nu = nvalid ? row[nidx] : 0;
        uint4 ne0 = g_projh[nu * 16 + q * 2];
        uint4 ne1 = g_projh[nu * 16 + q * 2 + 1];
        uint4 nf0 = g_feath[nu * 16 + q * 2];
        uint4 nf1 = g_feath[nu * 16 + q * 2 + 1];
        float npa = g_pa06[nu];

        __half2 el[8] = { *(__half2*)&e0.x, *(__half2*)&e0.y, *(__half2*)&e0.z, *(__half2*)&e0.w,
                          *(__half2*)&e1.x, *(__half2*)&e1.y, *(__half2*)&e1.z, *(__half2*)&e1.w };
        __half2 s1ab = zero2, s2 = zero2;
        #pragma unroll
        for (int c = 0; c < 8; c++) {
            __half2 x = __hadd2(el[c], er[c]);
            s1ab = __hfma2(__habs2(x), a[c], s1ab);
            s2   = __hfma2(el[c], er[c], s2);
        }
        __half2 pk = __hadd2(__lows2half2(s1ab, s2), __highs2half2(s1ab, s2));
        #pragma unroll
        for (int o = 1; o < 8; o <<= 1) {
            unsigned pku = *(unsigned*)&pk;
            unsigned ot = __shfl_xor_sync(0xffffffffu, pku, o);
            pk = __hadd2(pk, *(__half2*)&ot);
        }
        float s1 = __low2float(pk) + pa_u + c_v;
        float s2f = __high2float(pk);
        float gate = 1.f / (1.f + __expf(-s2f));
        float w = 1.f / (1.f + __expf(-s1 * gate));
        w = valid ? w : 0.f;
        __half2 w2 = __float2half2_rn(w);

        __half2 fu[8] = { *(__half2*)&f0.x, *(__half2*)&f0.y, *(__half2*)&f0.z, *(__half2*)&f0.w,
                          *(__half2*)&f1.x, *(__half2*)&f1.y, *(__half2*)&f1.z, *(__half2*)&f1.w };
        #pragma unroll
        for (int c = 0; c < 8; c++) acc[c] = __hfma2(fu[c], w2, acc[c]);

        idx = nidx; valid = nvalid; pa_u = npa;
        e0 = ne0; e1 = ne1; f0 = nf0; f1 = nf1;
    }

    #pragma unroll
    for (int c = 0; c < 8; c++) {
        unsigned x = *(unsigned*)&acc[c];
        unsigned y = __shfl_xor_sync(0xffffffffu, x, 8);
        acc[c] = __hadd2(acc[c], *(__half2*)&y);
        x = *(unsigned*)&acc[c];
        y = __shfl_xor_sync(0xffffffffu, x, 16);
        acc[c] = __hadd2(acc[c], *(__half2*)&y);
    }

    if (lane < 8) {
        float invd = (deg > 0) ? (1.f / (float)deg) : 0.f;
        float ge = 1.f + eps[0];
        const float4* fv = &((const float4*)feat)[v * 32 + lane * 4];
        float4* ov = &((float4*)out)[v * 32 + lane * 4];
        #pragma unroll
        for (int j = 0; j < 4; j++) {
            float2 lo = __half22float2(acc[2 * j]);
            float2 hi = __half22float2(acc[2 * j + 1]);
            float4 f = fv[j];
            float4 o;
            o.x = ge * f.x + lo.x * invd;
            o.y = ge * f.y + lo.y * invd;
            o.z = ge * f.z + hi.x * invd;
            o.w = ge * f.w + hi.y * invd;
            ov[j] = o;
        }
    }
}

// ---------------- launcher ----------------
extern "C" void kernel_launch(void* const* d_in, const int* in_sizes, int n_in,
                              void* d_out, int out_size) {
    const float* feat = (const float*)d_in[0];
    const float* fcw  = (const float*)d_in[1];
    const float* attn = (const float*)d_in[2];
    const float* eps  = (const float*)d_in[3];
    const int*   src  = (const int*)d_in[4];
    const int*   dst  = (const int*)d_in[5];

    int n = in_sizes[0] / DIM;
    int e = in_sizes[4];

    size_t smem = (size_t)(2 * DIM * SPITCH) * sizeof(__half);   // ~68KB
    cudaFuncSetAttribute(gemm_kernel, cudaFuncAttributeMaxDynamicSharedMemorySize, (int)smem);

    // launch 1: tensor-core GEMM (+ deg zero + feat->fp16 + pa06 + attn prep)
    gemm_kernel<<<(n + GROWS - 1) / GROWS, GTHREADS, smem>>>(feat, fcw, attn, n);
    // launch 2: bucket scatter (16 chains/thread)
    int e16 = (e + 15) / 16;
    scatter_kernel<<<(e16 + 255) / 256, 256>>>(src, dst, e);
    // launch 3: pipelined reduce
    int red_blocks = (n * 32 + 255) / 256;
    reduce_kernel<<<red_blocks, 256>>>(feat, eps, (float*)d_out, n);

    (void)n_in; (void)out_size;
}